// round 8
// baseline (speedup 1.0000x reference)
#include <cuda_runtime.h>
#include <cuda_bf16.h>
#include <cstdint>

#define Bz 32
#define Lz 200
#define Dz 768
#define Sz 1556
#define ROWCAP (Bz*Lz)
#define FEATN (Bz*Lz*Dz)
#define WPER  (Dz*Dz)

// ---------------- device scratch (static, no allocs) ----------------
__device__ int  g_offsets[Bz*9];
__device__ int  g_rowbase[8*Bz];
__device__ int  g_Mk[8];
__device__ int2 g_rows[8*ROWCAP];
__device__ __nv_bfloat16 g_featH[FEATN];
__device__ __nv_bfloat16 g_featL[FEATN];
#define WTOT (35*WPER)
__device__ __nv_bfloat16 g_WtH[WTOT];             // K-major [z][o][kk]
__device__ __nv_bfloat16 g_WtL[WTOT];

struct Ptrs7 { const float* p[7]; };

// ---------------- helpers ----------------
__device__ __forceinline__ uint32_t s2u(const void* p) {
    uint32_t a;
    asm("{ .reg .u64 t; cvta.to.shared.u64 t, %1; cvt.u32.u64 %0, t; }" : "=r"(a) : "l"(p));
    return a;
}
__device__ __forceinline__ void cpasync16(uint32_t s, const void* g) {
    asm volatile("cp.async.cg.shared.global [%0], [%1], 16;" :: "r"(s), "l"(g));
}
__device__ __forceinline__ void ldsm4(uint32_t* r, uint32_t a) {
    asm volatile("ldmatrix.sync.aligned.m8n8.x4.shared.b16 {%0,%1,%2,%3}, [%4];"
        : "=r"(r[0]), "=r"(r[1]), "=r"(r[2]), "=r"(r[3]) : "r"(a));
}
__device__ __forceinline__ void ldsm2(uint32_t* r, uint32_t a) {
    asm volatile("ldmatrix.sync.aligned.m8n8.x2.shared.b16 {%0,%1}, [%2];"
        : "=r"(r[0]), "=r"(r[1]) : "r"(a));
}
__device__ __forceinline__ void mma16816(float* c, const uint32_t* a, const uint32_t* b) {
    asm volatile("mma.sync.aligned.m16n8k16.row.col.f32.bf16.bf16.f32 "
        "{%0,%1,%2,%3}, {%4,%5,%6,%7}, {%8,%9}, {%0,%1,%2,%3};"
        : "+f"(c[0]), "+f"(c[1]), "+f"(c[2]), "+f"(c[3])
        : "r"(a[0]), "r"(a[1]), "r"(a[2]), "r"(a[3]), "r"(b[0]), "r"(b[1]));
}

// ---------------- prep: split features + split weights (no output zero) ----------------
__global__ void prep(const float* __restrict__ feat, Ptrs7 w) {
    int stride = gridDim.x * blockDim.x;
    int tid = blockIdx.x * blockDim.x + threadIdx.x;
    for (int i = tid; i < FEATN; i += stride) {
        float v = feat[i];
        __nv_bfloat16 h = __float2bfloat16(v);
        g_featH[i] = h;
        g_featL[i] = __float2bfloat16(v - __bfloat162float(h));
    }
    for (long i = tid; i < (long)WTOT; i += stride) {
        long r = i; int z = 0;
        while (r >= (long)(z + 2) * WPER) { r -= (long)(z + 2) * WPER; z++; }
        int K = Dz * (z + 2);
        int o = (int)(r / K), kk = (int)(r % K);
        int j = kk / Dz, ii = kk - j * Dz;
        float v = w.p[z][(long)o * K + ii * (z + 2) + j];
        __nv_bfloat16 h = __float2bfloat16(v);
        long dst = (long)(z * (z + 3) / 2) * WPER + r;
        g_WtH[dst] = h;
        g_WtL[dst] = __float2bfloat16(v - __bfloat162float(h));
    }
}

// ---------------- setup: lengths, offsets, per-k bases ----------------
__global__ void setup_kernel(const int* __restrict__ mask) {
    __shared__ int sh_n[Bz];
    int t = threadIdx.x;
    if (t < Bz) {
        int n = 0;
        #pragma unroll 8
        for (int i = 0; i < Lz; i++) n += mask[t*Lz + i];
        sh_n[t] = n;
        int off = 0;
        g_offsets[t*9 + 0] = 0;
        #pragma unroll
        for (int k = 0; k < 8; k++) {
            int c = n - k - 2; if (c < 0) c = 0;
            off += c;
            g_offsets[t*9 + k + 1] = off;
        }
    }
    __syncthreads();
    if (t < 8) {
        int k = t, run = 0;
        for (int b = 0; b < Bz; b++) {
            g_rowbase[k*Bz + b] = run;
            int c = sh_n[b] - k - 2; if (c < 0) c = 0;
            run += c;
        }
        g_Mk[k] = run;
    }
}

// ---------------- per-slot bucket/pos, build row lists ----------------
__global__ void build_rows() {
    int idx = blockIdx.x * blockDim.x + threadIdx.x;
    if (idx >= Bz*Sz) return;
    int b = idx / Sz, s = idx % Sz;
    const int* off = &g_offsets[b*9];
    int k = 0;
    #pragma unroll
    for (int m = 1; m < 8; m++) k += (off[m] <= s);
    if (s < off[8]) {
        int rel = s - off[k];
        int p = rel + 1;
        int r = g_rowbase[k*Bz + b] + rel;
        g_rows[k*ROWCAP + r] = make_int2(b*Lz + p, idx);
    }
}

// ---------------- finalize: zero invalid rows, write tail ----------------
__global__ void finalize(float* __restrict__ out, int write_tail) {
    int idx = blockIdx.x;                 // 0 .. B*S-1
    int b = idx / Sz, s = idx % Sz;
    int valid = (s < g_offsets[b*9 + 8]);
    if (!valid) {
        float4* d = (float4*)(out + (size_t)idx * Dz);
        d[threadIdx.x] = make_float4(0.f, 0.f, 0.f, 0.f);
    }
    if (write_tail && threadIdx.x == 0)
        out[(size_t)Bz*Sz*Dz + idx] = valid ? 1.0f : 0.0f;
}

// ---------------- bucket 0: exact fp32 row copy ----------------
__global__ void copy_k0(const float* __restrict__ feat, float* __restrict__ out) {
    int r = blockIdx.x;
    if (r >= g_Mk[0]) return;
    int2 rc = g_rows[r];
    const float4* __restrict__ s = (const float4*)(feat + (size_t)rc.x * Dz);
    float4* __restrict__ d = (float4*)(out + (size_t)rc.y * Dz);
    d[threadIdx.x] = s[threadIdx.x];
}

// ---------------- mma.sync gathered GEMM, buckets k=1..7 ----------------
// CTA tile 256x128, 512 thr (4x4 warps, warp tile 64x32). K-chunk 32 bf16,
// 64B packed rows + XOR swizzle. 4 stages x 48KB; one wait+barrier per 2 chunks.
// Split terms per chunk: D += AH*BH + AH*BL + AL*BH (fp32 accum).
#define TILE_A  16384           /* 256 rows x 64B */
#define TILE_BB 8192            /* 128 rows x 64B */
#define STAGE_B 49152           /* AH,AL,BH,BL */
#define SMEMREQ (4*STAGE_B)
__global__ void __launch_bounds__(512, 1) mma_gemm(Ptrs7 bias, float* __restrict__ out) {
    int z = 6 - blockIdx.z;             // heavy buckets first
    int Mk = g_Mk[z + 1];
    int m0 = blockIdx.y * 256;
    if (m0 >= Mk) return;
    int Ktot = Dz * (z + 2);
    int n0 = blockIdx.x * 128;
    int t = threadIdx.x;
    int w = t >> 5, lane = t & 31;
    int wm = w >> 2, wn = w & 3;        // 4 x 4 warp grid

    __shared__ int s_src[256], s_dst[256];
    extern __shared__ __align__(16) char smem[];
    uint32_t smem_u = s2u(smem);

    if (t < 256) {
        int gr = m0 + t;
        if (gr < Mk) {
            int2 rc = g_rows[(z+1)*ROWCAP + gr];
            s_src[t] = rc.x * Dz;
            s_dst[t] = rc.y;
        } else { s_src[t] = 0; s_dst[t] = -1; }
    }
    __syncthreads();

    // A loader: thread t -> row t>>1 (0..255), chunks cq, cq+1
    int rA = t >> 1, cq = (t & 1) << 1;
    int swA = (rA >> 1) & 3;
    uint32_t offA0 = (uint32_t)rA * 64 + (uint32_t)((cq       ^ swA) << 4);
    uint32_t offA1 = (uint32_t)rA * 64 + (uint32_t)(((cq + 1) ^ swA) << 4);
    const __nv_bfloat16* gAH = g_featH + s_src[rA] + cq*8;
    const __nv_bfloat16* gAL = g_featL + s_src[rA] + cq*8;
    // B loader: thread t -> row t>>2 (0..127), chunk t&3
    int rB = t >> 2, cB = t & 3;
    int swB = (rB >> 1) & 3;
    uint32_t offB = (uint32_t)rB * 64 + (uint32_t)((cB ^ swB) << 4);
    long wzb = (long)(z*(z+3)/2) * WPER;
    const __nv_bfloat16* gBH = g_WtH + wzb + (long)(n0 + rB) * Ktot + cB*8;
    const __nv_bfloat16* gBL = g_WtL + wzb + (long)(n0 + rB) * Ktot + cB*8;

    // ldmatrix per-lane bases
    int l8 = lane & 7;
    int rowA = wm*64 + l8 + ((lane >> 3) & 1) * 8;
    int rowB = wn*32 + l8;
    uint32_t swzA = (uint32_t)((rowA >> 1) & 3);
    uint32_t swzB = (uint32_t)((rowB >> 1) & 3);
    uint32_t cA0 = (lane >> 4) & 1;
    uint32_t cB0 = (lane >> 3) & 1;
    uint32_t aRow[4], bRow[4];
    #pragma unroll
    for (int mf = 0; mf < 4; mf++) aRow[mf] = (uint32_t)(rowA + mf*16) * 64;
    #pragma unroll
    for (int nf = 0; nf < 4; nf++) bRow[nf] = (uint32_t)(rowB + nf*8) * 64;

    float acc[4][4][4];
    #pragma unroll
    for (int i = 0; i < 4; i++)
        #pragma unroll
        for (int j = 0; j < 4; j++)
            #pragma unroll
            for (int r = 0; r < 4; r++) acc[i][j][r] = 0.f;

    int nch = Ktot / 32;                // 24*(z+2): even, >= 48

    // prologue: chunks 0..3 -> stages 0..3
    #pragma unroll
    for (int p = 0; p < 4; p++) {
        uint32_t sb = smem_u + (uint32_t)p * STAGE_B;
        int ko = p * 32;
        cpasync16(sb + 0*TILE_A  + offA0, gAH + ko); cpasync16(sb + 0*TILE_A  + offA1, gAH + ko + 8);
        cpasync16(sb + 1*TILE_A  + offA0, gAL + ko); cpasync16(sb + 1*TILE_A  + offA1, gAL + ko + 8);
        cpasync16(sb + 32768     + offB,  gBH + ko);
        cpasync16(sb + 40960     + offB,  gBL + ko);
        asm volatile("cp.async.commit_group;" ::: "memory");
    }

    #pragma unroll 1
    for (int c = 0; c < nch; c += 2) {
        asm volatile("cp.async.wait_group 2;" ::: "memory");   // chunks c, c+1 landed
        __syncthreads();

        #pragma unroll
        for (int h = 0; h < 2; h++) {
            uint32_t sb = smem_u + (uint32_t)((c + h) & 3) * STAGE_B;
            #pragma unroll
            for (int ks = 0; ks < 2; ks++) {
                uint32_t colA = ((cA0 + 2*ks) ^ swzA) << 4;
                uint32_t colB = ((cB0 + 2*ks) ^ swzB) << 4;
                uint32_t ah[4][4], bh[4][2];
                #pragma unroll
                for (int mf = 0; mf < 4; mf++) ldsm4(ah[mf], sb + 0*TILE_A + aRow[mf] + colA);
                #pragma unroll
                for (int nf = 0; nf < 4; nf++) ldsm2(bh[nf], sb + 32768 + bRow[nf] + colB);
                #pragma unroll
                for (int mf = 0; mf < 4; mf++)
                    #pragma unroll
                    for (int nf = 0; nf < 4; nf++) mma16816(acc[mf][nf], ah[mf], bh[nf]);

                uint32_t bl[4][2];
                #pragma unroll
                for (int nf = 0; nf < 4; nf++) ldsm2(bl[nf], sb + 40960 + bRow[nf] + colB);
                #pragma unroll
                for (int mf = 0; mf < 4; mf++)
                    #pragma unroll
                    for (int nf = 0; nf < 4; nf++) mma16816(acc[mf][nf], ah[mf], bl[nf]);

                uint32_t al[4][4];
                #pragma unroll
                for (int mf = 0; mf < 4; mf++) ldsm4(al[mf], sb + 1*TILE_A + aRow[mf] + colA);
                #pragma unroll
                for (int mf = 0; mf < 4; mf++)
                    #pragma unroll
                    for (int nf = 0; nf < 4; nf++) mma16816(acc[mf][nf], al[mf], bh[nf]);
            }
        }
        __syncthreads();                                       // reads of c, c+1 done
        #pragma unroll
        for (int h = 0; h < 2; h++) {
            if (c + 4 + h < nch) {
                uint32_t nb = smem_u + (uint32_t)((c + h) & 3) * STAGE_B;
                int ko = (c + 4 + h) * 32;
                cpasync16(nb + 0*TILE_A  + offA0, gAH + ko); cpasync16(nb + 0*TILE_A  + offA1, gAH + ko + 8);
                cpasync16(nb + 1*TILE_A  + offA0, gAL + ko); cpasync16(nb + 1*TILE_A  + offA1, gAL + ko + 8);
                cpasync16(nb + 32768     + offB,  gBH + ko);
                cpasync16(nb + 40960     + offB,  gBL + ko);
            }
            asm volatile("cp.async.commit_group;" ::: "memory");
        }
    }
    asm volatile("cp.async.wait_group 0;" ::: "memory");

    // epilogue: bias + scatter to gathered dst rows
    int r0 = wm*64 + (lane >> 2);
    int cb = n0 + wn*32 + ((lane & 3) << 1);
    const float* bpz = bias.p[z];
    #pragma unroll
    for (int mf = 0; mf < 4; mf++) {
        int row = r0 + mf*16;
        int d0 = s_dst[row], d1 = s_dst[row + 8];
        #pragma unroll
        for (int nf = 0; nf < 4; nf++) {
            float2 bv = *(const float2*)(bpz + cb + nf*8);
            if (d0 >= 0) {
                float2 v; v.x = acc[mf][nf][0] + bv.x; v.y = acc[mf][nf][1] + bv.y;
                *(float2*)(out + (long)d0*Dz + cb + nf*8) = v;
            }
            if (d1 >= 0) {
                float2 v; v.x = acc[mf][nf][2] + bv.x; v.y = acc[mf][nf][3] + bv.y;
                *(float2*)(out + (long)d1*Dz + cb + nf*8) = v;
            }
        }
    }
}

// ---------------- launch ----------------
extern "C" void kernel_launch(void* const* d_in, const int* in_sizes, int n_in,
                              void* d_out, int out_size) {
    const float* feat = (const float*)d_in[0];
    const int*   mask = (const int*)d_in[1];
    // d_in[2] = span_mask (unused; shape only)

    Ptrs7 wp, bp;
    int wi = 0, bi = 0;
    for (int i = 3; i < n_in && i < 17; i++) {
        if (in_sizes[i] == Dz) { if (bi < 7) bp.p[bi++] = (const float*)d_in[i]; }
        else                   { if (wi < 7) wp.p[wi++] = (const float*)d_in[i]; }
    }
    float* out = (float*)d_out;

    prep<<<2048, 256>>>(feat, wp);                                     // launch 1
    setup_kernel<<<1, 64>>>(mask);                                     // launch 2
    build_rows<<<(Bz*Sz + 255) / 256, 256>>>();                        // launch 3

    cudaFuncSetAttribute(mma_gemm, cudaFuncAttributeMaxDynamicSharedMemorySize, SMEMREQ);
    mma_gemm<<<dim3(6, 25, 7), 512, SMEMREQ>>>(bp, out);               // launch 4 (profiled)

    int tail = (out_size >= Bz*Sz*Dz + Bz*Sz) ? 1 : 0;
    finalize<<<Bz*Sz, 192>>>(out, tail);                               // launch 5
    copy_k0<<<Bz*(Lz - 2), 192>>>(feat, out);                          // launch 6
}

// round 9
// speedup vs baseline: 1.0030x; 1.0030x over previous
#include <cuda_runtime.h>
#include <cuda_bf16.h>
#include <cstdint>

#define Bz 32
#define Lz 200
#define Dz 768
#define Sz 1556
#define ROWCAP (Bz*Lz)
#define FEATN (Bz*Lz*Dz)
#define WPER  (Dz*Dz)

// ---------------- device scratch (static, no allocs) ----------------
__device__ int  g_offsets[Bz*9];
__device__ int  g_rowbase[8*Bz];
__device__ int  g_Mk[8];
__device__ int2 g_rows[8*ROWCAP];
__device__ __nv_bfloat16 g_featH[FEATN];
__device__ __nv_bfloat16 g_featL[FEATN];
#define WTOT (35*WPER)
__device__ __nv_bfloat16 g_WtH[WTOT];             // K-major [z][o][kk]
__device__ __nv_bfloat16 g_WtL[WTOT];

struct Ptrs7 { const float* p[7]; };

// ---------------- helpers ----------------
__device__ __forceinline__ uint32_t s2u(const void* p) {
    uint32_t a;
    asm("{ .reg .u64 t; cvta.to.shared.u64 t, %1; cvt.u32.u64 %0, t; }" : "=r"(a) : "l"(p));
    return a;
}
__device__ __forceinline__ void cpasync16(uint32_t s, const void* g) {
    asm volatile("cp.async.cg.shared.global [%0], [%1], 16;" :: "r"(s), "l"(g));
}
__device__ __forceinline__ void ldsm4(uint32_t* r, uint32_t a) {
    asm volatile("ldmatrix.sync.aligned.m8n8.x4.shared.b16 {%0,%1,%2,%3}, [%4];"
        : "=r"(r[0]), "=r"(r[1]), "=r"(r[2]), "=r"(r[3]) : "r"(a));
}
__device__ __forceinline__ void mma16816(float* c, const uint32_t* a, const uint32_t* b) {
    asm volatile("mma.sync.aligned.m16n8k16.row.col.f32.bf16.bf16.f32 "
        "{%0,%1,%2,%3}, {%4,%5,%6,%7}, {%8,%9}, {%0,%1,%2,%3};"
        : "+f"(c[0]), "+f"(c[1]), "+f"(c[2]), "+f"(c[3])
        : "r"(a[0]), "r"(a[1]), "r"(a[2]), "r"(a[3]), "r"(b[0]), "r"(b[1]));
}

// ---------------- prep: split features + split weights ----------------
__global__ void prep(const float* __restrict__ feat, Ptrs7 w) {
    int stride = gridDim.x * blockDim.x;
    int tid = blockIdx.x * blockDim.x + threadIdx.x;
    for (int i = tid; i < FEATN; i += stride) {
        float v = feat[i];
        __nv_bfloat16 h = __float2bfloat16(v);
        g_featH[i] = h;
        g_featL[i] = __float2bfloat16(v - __bfloat162float(h));
    }
    for (long i = tid; i < (long)WTOT; i += stride) {
        long r = i; int z = 0;
        while (r >= (long)(z + 2) * WPER) { r -= (long)(z + 2) * WPER; z++; }
        int K = Dz * (z + 2);
        int o = (int)(r / K), kk = (int)(r % K);
        int j = kk / Dz, ii = kk - j * Dz;
        float v = w.p[z][(long)o * K + ii * (z + 2) + j];
        __nv_bfloat16 h = __float2bfloat16(v);
        long dst = (long)(z * (z + 3) / 2) * WPER + r;
        g_WtH[dst] = h;
        g_WtL[dst] = __float2bfloat16(v - __bfloat162float(h));
    }
}

// ---------------- setup: lengths, offsets, per-k bases ----------------
__global__ void setup_kernel(const int* __restrict__ mask) {
    __shared__ int sh_n[Bz];
    int t = threadIdx.x;
    if (t < Bz) {
        int n = 0;
        #pragma unroll 8
        for (int i = 0; i < Lz; i++) n += mask[t*Lz + i];
        sh_n[t] = n;
        int off = 0;
        g_offsets[t*9 + 0] = 0;
        #pragma unroll
        for (int k = 0; k < 8; k++) {
            int c = n - k - 2; if (c < 0) c = 0;
            off += c;
            g_offsets[t*9 + k + 1] = off;
        }
    }
    __syncthreads();
    if (t < 8) {
        int k = t, run = 0;
        for (int b = 0; b < Bz; b++) {
            g_rowbase[k*Bz + b] = run;
            int c = sh_n[b] - k - 2; if (c < 0) c = 0;
            run += c;
        }
        g_Mk[k] = run;
    }
}

// ---------------- per-slot bucket/pos, build row lists ----------------
__global__ void build_rows() {
    int idx = blockIdx.x * blockDim.x + threadIdx.x;
    if (idx >= Bz*Sz) return;
    int b = idx / Sz, s = idx % Sz;
    const int* off = &g_offsets[b*9];
    int k = 0;
    #pragma unroll
    for (int m = 1; m < 8; m++) k += (off[m] <= s);
    if (s < off[8]) {
        int rel = s - off[k];
        int p = rel + 1;
        int r = g_rowbase[k*Bz + b] + rel;
        g_rows[k*ROWCAP + r] = make_int2(b*Lz + p, idx);
    }
}

// ---------------- finalize: zero invalid rows, write tail ----------------
__global__ void finalize(float* __restrict__ out, int write_tail) {
    int idx = blockIdx.x;                 // 0 .. B*S-1
    int b = idx / Sz, s = idx % Sz;
    int valid = (s < g_offsets[b*9 + 8]);
    if (!valid) {
        float4* d = (float4*)(out + (size_t)idx * Dz);
        d[threadIdx.x] = make_float4(0.f, 0.f, 0.f, 0.f);
    }
    if (write_tail && threadIdx.x == 0)
        out[(size_t)Bz*Sz*Dz + idx] = valid ? 1.0f : 0.0f;
}

// ---------------- bucket 0: exact fp32 row copy ----------------
__global__ void copy_k0(const float* __restrict__ feat, float* __restrict__ out) {
    int r = blockIdx.x;
    if (r >= g_Mk[0]) return;
    int2 rc = g_rows[r];
    const float4* __restrict__ s = (const float4*)(feat + (size_t)rc.x * Dz);
    float4* __restrict__ d = (float4*)(out + (size_t)rc.y * Dz);
    d[threadIdx.x] = s[threadIdx.x];
}

// ---------------- mma.sync gathered GEMM, buckets k=1..7 ----------------
// CTA tile 256x128, 512 thr (4x4 warps, warp tile 64x32). K-chunk 32 bf16,
// 64B packed rows + XOR swizzle. 4 stages x 48KB; one wait+barrier per 2 chunks.
// Per ks: ALL 12 ldsm up front (ah, bh, bl, al), then 48 MMAs (AH*BH, AH*BL, AL*BH).
#define TILE_A  16384           /* 256 rows x 64B */
#define STAGE_B 49152           /* AH,AL @0/16K, BH @32K, BL @40K */
#define SMEMREQ (4*STAGE_B)
__global__ void __launch_bounds__(512, 1) mma_gemm(Ptrs7 bias, float* __restrict__ out) {
    int z = 6 - blockIdx.z;             // heavy buckets first
    int Mk = g_Mk[z + 1];
    int m0 = blockIdx.y * 256;
    if (m0 >= Mk) return;
    int Ktot = Dz * (z + 2);
    int n0 = blockIdx.x * 128;
    int t = threadIdx.x;
    int w = t >> 5, lane = t & 31;
    int wm = w >> 2, wn = w & 3;        // 4 x 4 warp grid

    __shared__ int s_src[256], s_dst[256];
    extern __shared__ __align__(16) char smem[];
    uint32_t smem_u = s2u(smem);

    if (t < 256) {
        int gr = m0 + t;
        if (gr < Mk) {
            int2 rc = g_rows[(z+1)*ROWCAP + gr];
            s_src[t] = rc.x * Dz;
            s_dst[t] = rc.y;
        } else { s_src[t] = 0; s_dst[t] = -1; }
    }
    __syncthreads();

    // A loader: thread t -> row t>>1 (0..255), chunks cq, cq+1
    int rA = t >> 1, cq = (t & 1) << 1;
    int swA = (rA >> 1) & 3;
    uint32_t offA0 = (uint32_t)rA * 64 + (uint32_t)((cq       ^ swA) << 4);
    uint32_t offA1 = (uint32_t)rA * 64 + (uint32_t)(((cq + 1) ^ swA) << 4);
    const __nv_bfloat16* gAH = g_featH + s_src[rA] + cq*8;
    const __nv_bfloat16* gAL = g_featL + s_src[rA] + cq*8;
    // B loader: thread t -> row t>>2 (0..127), chunk t&3
    int rB = t >> 2, cB = t & 3;
    int swB = (rB >> 1) & 3;
    uint32_t offB = (uint32_t)rB * 64 + (uint32_t)((cB ^ swB) << 4);
    long wzb = (long)(z*(z+3)/2) * WPER;
    const __nv_bfloat16* gBH = g_WtH + wzb + (long)(n0 + rB) * Ktot + cB*8;
    const __nv_bfloat16* gBL = g_WtL + wzb + (long)(n0 + rB) * Ktot + cB*8;

    // ldmatrix per-lane bases
    int l8 = lane & 7;
    // A: x4 frags, rows wm*64 + l8 + ((lane>>3)&1)*8, col half (lane>>4)&1
    int rowA = wm*64 + l8 + ((lane >> 3) & 1) * 8;
    uint32_t swzA = (uint32_t)((rowA >> 1) & 3);
    uint32_t cA0 = (lane >> 4) & 1;
    uint32_t aRow[4];
    #pragma unroll
    for (int mf = 0; mf < 4; mf++) aRow[mf] = (uint32_t)(rowA + mf*16) * 64;
    // B: x4 pair frags. lane -> matrix: pairSel=(lane>>4)&1 (rows +8), colSel=(lane>>3)&1 (k-half)
    int rowB4 = wn*32 + l8 + ((lane >> 4) & 1) * 8;
    uint32_t swzB = (uint32_t)((rowB4 >> 1) & 3);   // invariant under +8/+16 row offsets
    uint32_t cB0 = (lane >> 3) & 1;
    uint32_t bRow[2];
    #pragma unroll
    for (int pb = 0; pb < 2; pb++) bRow[pb] = (uint32_t)(rowB4 + pb*16) * 64;

    float acc[4][4][4];
    #pragma unroll
    for (int i = 0; i < 4; i++)
        #pragma unroll
        for (int j = 0; j < 4; j++)
            #pragma unroll
            for (int r = 0; r < 4; r++) acc[i][j][r] = 0.f;

    int nch = Ktot / 32;                // 24*(z+2): even, >= 48

    // prologue: chunks 0..3 -> stages 0..3
    #pragma unroll
    for (int p = 0; p < 4; p++) {
        uint32_t sb = smem_u + (uint32_t)p * STAGE_B;
        int ko = p * 32;
        cpasync16(sb + 0*TILE_A + offA0, gAH + ko); cpasync16(sb + 0*TILE_A + offA1, gAH + ko + 8);
        cpasync16(sb + 1*TILE_A + offA0, gAL + ko); cpasync16(sb + 1*TILE_A + offA1, gAL + ko + 8);
        cpasync16(sb + 32768    + offB,  gBH + ko);
        cpasync16(sb + 40960    + offB,  gBL + ko);
        asm volatile("cp.async.commit_group;" ::: "memory");
    }

    #pragma unroll 1
    for (int c = 0; c < nch; c += 2) {
        asm volatile("cp.async.wait_group 2;" ::: "memory");   // chunks c, c+1 landed
        __syncthreads();

        #pragma unroll
        for (int h = 0; h < 2; h++) {
            uint32_t sb = smem_u + (uint32_t)((c + h) & 3) * STAGE_B;
            #pragma unroll
            for (int ks = 0; ks < 2; ks++) {
                uint32_t colA = ((cA0 + 2*ks) ^ swzA) << 4;
                uint32_t colB = ((cB0 + 2*ks) ^ swzB) << 4;
                // ---- all fragment loads first (deps for first MMAs load earliest) ----
                uint32_t ah[4][4], bh[2][4], bl[2][4], al[4][4];
                #pragma unroll
                for (int mf = 0; mf < 4; mf++) ldsm4(ah[mf], sb + 0*TILE_A + aRow[mf] + colA);
                #pragma unroll
                for (int pb = 0; pb < 2; pb++) ldsm4(bh[pb], sb + 32768 + bRow[pb] + colB);
                #pragma unroll
                for (int pb = 0; pb < 2; pb++) ldsm4(bl[pb], sb + 40960 + bRow[pb] + colB);
                #pragma unroll
                for (int mf = 0; mf < 4; mf++) ldsm4(al[mf], sb + 1*TILE_A + aRow[mf] + colA);
                // ---- 48 MMAs ----
                #pragma unroll
                for (int mf = 0; mf < 4; mf++) {
                    mma16816(acc[mf][0], ah[mf], &bh[0][0]);
                    mma16816(acc[mf][1], ah[mf], &bh[0][2]);
                    mma16816(acc[mf][2], ah[mf], &bh[1][0]);
                    mma16816(acc[mf][3], ah[mf], &bh[1][2]);
                }
                #pragma unroll
                for (int mf = 0; mf < 4; mf++) {
                    mma16816(acc[mf][0], ah[mf], &bl[0][0]);
                    mma16816(acc[mf][1], ah[mf], &bl[0][2]);
                    mma16816(acc[mf][2], ah[mf], &bl[1][0]);
                    mma16816(acc[mf][3], ah[mf], &bl[1][2]);
                }
                #pragma unroll
                for (int mf = 0; mf < 4; mf++) {
                    mma16816(acc[mf][0], al[mf], &bh[0][0]);
                    mma16816(acc[mf][1], al[mf], &bh[0][2]);
                    mma16816(acc[mf][2], al[mf], &bh[1][0]);
                    mma16816(acc[mf][3], al[mf], &bh[1][2]);
                }
            }
        }
        __syncthreads();                                       // reads of c, c+1 done
        #pragma unroll
        for (int h = 0; h < 2; h++) {
            if (c + 4 + h < nch) {
                uint32_t nb = smem_u + (uint32_t)((c + h) & 3) * STAGE_B;
                int ko = (c + 4 + h) * 32;
                cpasync16(nb + 0*TILE_A + offA0, gAH + ko); cpasync16(nb + 0*TILE_A + offA1, gAH + ko + 8);
                cpasync16(nb + 1*TILE_A + offA0, gAL + ko); cpasync16(nb + 1*TILE_A + offA1, gAL + ko + 8);
                cpasync16(nb + 32768    + offB,  gBH + ko);
                cpasync16(nb + 40960    + offB,  gBL + ko);
            }
            asm volatile("cp.async.commit_group;" ::: "memory");
        }
    }
    asm volatile("cp.async.wait_group 0;" ::: "memory");

    // epilogue: bias + scatter to gathered dst rows
    int r0 = wm*64 + (lane >> 2);
    int cb = n0 + wn*32 + ((lane & 3) << 1);
    const float* bpz = bias.p[z];
    #pragma unroll
    for (int mf = 0; mf < 4; mf++) {
        int row = r0 + mf*16;
        int d0 = s_dst[row], d1 = s_dst[row + 8];
        #pragma unroll
        for (int nf = 0; nf < 4; nf++) {
            float2 bv = *(const float2*)(bpz + cb + nf*8);
            if (d0 >= 0) {
                float2 v; v.x = acc[mf][nf][0] + bv.x; v.y = acc[mf][nf][1] + bv.y;
                *(float2*)(out + (long)d0*Dz + cb + nf*8) = v;
            }
            if (d1 >= 0) {
                float2 v; v.x = acc[mf][nf][2] + bv.x; v.y = acc[mf][nf][3] + bv.y;
                *(float2*)(out + (long)d1*Dz + cb + nf*8) = v;
            }
        }
    }
}

// ---------------- launch ----------------
extern "C" void kernel_launch(void* const* d_in, const int* in_sizes, int n_in,
                              void* d_out, int out_size) {
    const float* feat = (const float*)d_in[0];
    const int*   mask = (const int*)d_in[1];
    // d_in[2] = span_mask (unused; shape only)

    Ptrs7 wp, bp;
    int wi = 0, bi = 0;
    for (int i = 3; i < n_in && i < 17; i++) {
        if (in_sizes[i] == Dz) { if (bi < 7) bp.p[bi++] = (const float*)d_in[i]; }
        else                   { if (wi < 7) wp.p[wi++] = (const float*)d_in[i]; }
    }
    float* out = (float*)d_out;

    prep<<<2048, 256>>>(feat, wp);                                     // launch 1
    setup_kernel<<<1, 64>>>(mask);                                     // launch 2
    build_rows<<<(Bz*Sz + 255) / 256, 256>>>();                        // launch 3

    cudaFuncSetAttribute(mma_gemm, cudaFuncAttributeMaxDynamicSharedMemorySize, SMEMREQ);
    mma_gemm<<<dim3(6, 25, 7), 512, SMEMREQ>>>(bp, out);               // launch 4 (profiled)

    int tail = (out_size >= Bz*Sz*Dz + Bz*Sz) ? 1 : 0;
    finalize<<<Bz*Sz, 192>>>(out, tail);                               // launch 5
    copy_k0<<<Bz*(Lz - 2), 192>>>(feat, out);                          // launch 6
}